// round 3
// baseline (speedup 1.0000x reference)
#include <cuda_runtime.h>

// Problem constants
#define BB 1024
#define NN 4096
#define NTH 256
#define NWARP (NTH / 32)
#define NACC 23

// Accumulator layout:
//  0..5  : Mw symmetric (00,01,02,11,12,22)
//  6..8  : mw
//  9..11 : yw
// 12..20 : MY[i*3+j]
// 21     : sw
// 22     : yy

__device__ __forceinline__ void accum_point(float acc[NACC],
                                            float m0, float m1, float m2,
                                            float y0, float y1, float y2,
                                            float w) {
    float wm0 = w * m0, wm1 = w * m1, wm2 = w * m2;
    acc[0]  += wm0 * m0;
    acc[1]  += wm0 * m1;
    acc[2]  += wm0 * m2;
    acc[3]  += wm1 * m1;
    acc[4]  += wm1 * m2;
    acc[5]  += wm2 * m2;
    acc[6]  += wm0;
    acc[7]  += wm1;
    acc[8]  += wm2;
    float wy0 = w * y0, wy1 = w * y1, wy2 = w * y2;
    acc[9]  += wy0;
    acc[10] += wy1;
    acc[11] += wy2;
    acc[12] += wm0 * y0;
    acc[13] += wm0 * y1;
    acc[14] += wm0 * y2;
    acc[15] += wm1 * y0;
    acc[16] += wm1 * y1;
    acc[17] += wm1 * y2;
    acc[18] += wm2 * y0;
    acc[19] += wm2 * y1;
    acc[20] += wm2 * y2;
    acc[21] += w;
    acc[22] += wy0 * y0 + wy1 * y1 + wy2 * y2;
}

// symmetric 3x3 index into acc[0..5]
__device__ __forceinline__ int sym_idx(int i, int j) {
    if (i > j) { int t = i; i = j; j = t; }
    return i * (5 - i) / 2 + j;
}

__global__ __launch_bounds__(NTH, 8)
void locblock_kernel(const float* __restrict__ src,
                     const float* __restrict__ trg,
                     const float* __restrict__ wts,
                     float* __restrict__ out) {
    const int b   = blockIdx.x;
    const int tid = threadIdx.x;

    const float* m0p = src + (size_t)b * 3 * NN;
    const float* m1p = m0p + NN;
    const float* m2p = m1p + NN;
    const float* y0p = trg + (size_t)b * 3 * NN;
    const float* y1p = y0p + NN;
    const float* y2p = y1p + NN;
    const float* wp  = wts + (size_t)b * NN;

    float acc[NACC];
#pragma unroll
    for (int k = 0; k < NACC; k++) acc[k] = 0.f;

    // Vectorized streaming loop: 4096 / (256*4) = 4 iterations
#pragma unroll
    for (int it = 0; it < NN / (NTH * 4); it++) {
        int n = (it * NTH + tid) * 4;
        float4 a0 = *(const float4*)(m0p + n);
        float4 a1 = *(const float4*)(m1p + n);
        float4 a2 = *(const float4*)(m2p + n);
        float4 b0 = *(const float4*)(y0p + n);
        float4 b1 = *(const float4*)(y1p + n);
        float4 b2 = *(const float4*)(y2p + n);
        float4 wv = *(const float4*)(wp  + n);
        accum_point(acc, a0.x, a1.x, a2.x, b0.x, b1.x, b2.x, wv.x);
        accum_point(acc, a0.y, a1.y, a2.y, b0.y, b1.y, b2.y, wv.y);
        accum_point(acc, a0.z, a1.z, a2.z, b0.z, b1.z, b2.z, wv.z);
        accum_point(acc, a0.w, a1.w, a2.w, b0.w, b1.w, b2.w, wv.w);
    }

    // Intra-warp shuffle reduction
#pragma unroll
    for (int k = 0; k < NACC; k++) {
#pragma unroll
        for (int off = 16; off > 0; off >>= 1)
            acc[k] += __shfl_xor_sync(0xFFFFFFFFu, acc[k], off);
    }

    __shared__ float sred[NWARP][NACC];
    __shared__ float fin[NACC];
    __shared__ float s_inv_scale;
    __shared__ float s_scale;

    const int warp = tid >> 5;
    const int lane = tid & 31;
    if (lane == 0) {
#pragma unroll
        for (int k = 0; k < NACC; k++) sred[warp][k] = acc[k];
    }
    __syncthreads();

    if (tid < NACC) {
        float s = 0.f;
#pragma unroll
        for (int wI = 0; wI < NWARP; wI++) s += sred[wI][tid];
        fin[tid] = s;
    }
    __syncthreads();

    if (tid == 0) {
        // scale^2 = 3*sum(Mw^2) + 6*sum(mw^2) + 2*sum(MY^2) + 2*sum(yw^2) + 3*sw^2
        float sumMw2 = fin[0] * fin[0] + fin[3] * fin[3] + fin[5] * fin[5]
                     + 2.f * (fin[1] * fin[1] + fin[2] * fin[2] + fin[4] * fin[4]);
        float summw2 = fin[6] * fin[6] + fin[7] * fin[7] + fin[8] * fin[8];
        float sumyw2 = fin[9] * fin[9] + fin[10] * fin[10] + fin[11] * fin[11];
        float sumMY2 = 0.f;
#pragma unroll
        for (int k = 12; k < 21; k++) sumMY2 += fin[k] * fin[k];
        float sw = fin[21];
        float sc2 = 3.f * sumMw2 + 6.f * summw2 + 2.f * sumMY2 + 2.f * sumyw2 + 3.f * sw * sw;
        float sc = sqrtf(sc2);
        s_scale = sc;
        s_inv_scale = 1.f / sc;
    }
    __syncthreads();

    // Assemble + write Qn: 169 entries, one per thread
    float* Qn      = out;                           // [B][13][13]
    float* scales  = out + (size_t)BB * 169;        // [B]
    float* offsets = out + (size_t)BB * 169 + BB;   // [B]

    if (tid < 169) {
        int r = tid / 13;
        int c = tid % 13;
        float v = 0.f;
        if (r >= 1 && r <= 9) {
            int a = r - 1;
            int i = a / 3, k = a % 3;
            if (c >= 1 && c <= 9) {
                int bq = c - 1;
                int j = bq / 3, l = bq % 3;
                if (k == l) v = fin[sym_idx(i, j)];       // Qcc
            } else if (c >= 10) {
                int l = c - 10;
                if (k == l) v = -fin[6 + i];              // Qct
            } else { // c == 0
                v = -fin[12 + i * 3 + k];                 // Qch (a = i*3+j, here k==j)
            }
        } else if (r >= 10) {
            int i_t = r - 10;
            if (c >= 1 && c <= 9) {
                int a = c - 1;
                int i = a / 3, k = a % 3;
                if (k == i_t) v = -fin[6 + i];            // Qct^T
            } else if (c >= 10) {
                if (r == c) v = fin[21];                  // Qtt
            } else { // c == 0
                v = fin[9 + i_t];                         // yw
            }
        } else { // r == 0
            if (c >= 1 && c <= 9) {
                int a = c - 1;
                v = -fin[12 + a];                         // Qch row
            } else if (c >= 10) {
                v = fin[9 + (c - 10)];                    // yw row
            }
            // c == 0 -> 0
        }
        Qn[(size_t)b * 169 + tid] = v * s_inv_scale;
    }
    if (tid == 169) scales[b] = s_scale;
    if (tid == 170) offsets[b] = fin[22];
}

extern "C" void kernel_launch(void* const* d_in, const int* in_sizes, int n_in,
                              void* d_out, int out_size) {
    const float* src = (const float*)d_in[0];
    const float* trg = (const float*)d_in[1];
    const float* wts = (const float*)d_in[2];
    float* out = (float*)d_out;
    locblock_kernel<<<BB, NTH>>>(src, trg, wts, out);
}

// round 6
// speedup vs baseline: 2.7042x; 2.7042x over previous
#include <cuda_runtime.h>

// Problem constants
#define BB 1024
#define NN 4096
#define NTH 128
#define NWARP (NTH / 32)
#define NACC 23
#define ITERS (NN / (NTH * 4))   // 8

// Accumulator layout:
//  0..5  : Mw symmetric (00,01,02,11,12,22)
//  6..8  : mw
//  9..11 : yw
// 12..20 : MY[i*3+j]
// 21     : sw
// 22     : yy

__device__ __forceinline__ void accum_point(float acc[NACC],
                                            float m0, float m1, float m2,
                                            float y0, float y1, float y2,
                                            float w) {
    float wm0 = w * m0, wm1 = w * m1, wm2 = w * m2;
    acc[0]  += wm0 * m0;
    acc[1]  += wm0 * m1;
    acc[2]  += wm0 * m2;
    acc[3]  += wm1 * m1;
    acc[4]  += wm1 * m2;
    acc[5]  += wm2 * m2;
    acc[6]  += wm0;
    acc[7]  += wm1;
    acc[8]  += wm2;
    float wy0 = w * y0, wy1 = w * y1, wy2 = w * y2;
    acc[9]  += wy0;
    acc[10] += wy1;
    acc[11] += wy2;
    acc[12] += wm0 * y0;
    acc[13] += wm0 * y1;
    acc[14] += wm0 * y2;
    acc[15] += wm1 * y0;
    acc[16] += wm1 * y1;
    acc[17] += wm1 * y2;
    acc[18] += wm2 * y0;
    acc[19] += wm2 * y1;
    acc[20] += wm2 * y2;
    acc[21] += w;
    acc[22] += wy0 * y0 + wy1 * y1 + wy2 * y2;
}

// symmetric 3x3 index into acc[0..5]
__device__ __forceinline__ int sym_idx(int i, int j) {
    if (i > j) { int t = i; i = j; j = t; }
    return i * (5 - i) / 2 + j;
}

__global__ __launch_bounds__(NTH, 8)
void locblock_kernel(const float* __restrict__ src,
                     const float* __restrict__ trg,
                     const float* __restrict__ wts,
                     float* __restrict__ out) {
    const int b   = blockIdx.x;
    const int tid = threadIdx.x;

    const float* m0p = src + (size_t)b * 3 * NN;
    const float* m1p = m0p + NN;
    const float* m2p = m1p + NN;
    const float* y0p = trg + (size_t)b * 3 * NN;
    const float* y1p = y0p + NN;
    const float* y2p = y1p + NN;
    const float* wp  = wts + (size_t)b * NN;

    float acc[NACC];
#pragma unroll
    for (int k = 0; k < NACC; k++) acc[k] = 0.f;

    // Vectorized streaming loop: 4096 / (128*4) = 8 iterations.
    // 7 independent float4 loads per iteration -> MLP ~= 7 per thread.
    // 64-reg budget (128 thr x 8 CTAs/SM) lets all 7 stay in flight.
#pragma unroll
    for (int it = 0; it < ITERS; it++) {
        int n = (it * NTH + tid) * 4;
        float4 a0 = *(const float4*)(m0p + n);
        float4 a1 = *(const float4*)(m1p + n);
        float4 a2 = *(const float4*)(m2p + n);
        float4 b0 = *(const float4*)(y0p + n);
        float4 b1 = *(const float4*)(y1p + n);
        float4 b2 = *(const float4*)(y2p + n);
        float4 wv = *(const float4*)(wp  + n);
        accum_point(acc, a0.x, a1.x, a2.x, b0.x, b1.x, b2.x, wv.x);
        accum_point(acc, a0.y, a1.y, a2.y, b0.y, b1.y, b2.y, wv.y);
        accum_point(acc, a0.z, a1.z, a2.z, b0.z, b1.z, b2.z, wv.z);
        accum_point(acc, a0.w, a1.w, a2.w, b0.w, b1.w, b2.w, wv.w);
    }

    // Intra-warp shuffle reduction
#pragma unroll
    for (int k = 0; k < NACC; k++) {
#pragma unroll
        for (int off = 16; off > 0; off >>= 1)
            acc[k] += __shfl_xor_sync(0xFFFFFFFFu, acc[k], off);
    }

    __shared__ float sred[NWARP][NACC];
    __shared__ float fin[NACC];
    __shared__ float s_inv_scale;
    __shared__ float s_scale;

    const int warp = tid >> 5;
    const int lane = tid & 31;
    if (lane == 0) {
#pragma unroll
        for (int k = 0; k < NACC; k++) sred[warp][k] = acc[k];
    }
    __syncthreads();

    if (tid < NACC) {
        float s = 0.f;
#pragma unroll
        for (int wI = 0; wI < NWARP; wI++) s += sred[wI][tid];
        fin[tid] = s;
    }
    __syncthreads();

    if (tid == 0) {
        // scale^2 = 3*sum(Mw^2) + 6*sum(mw^2) + 2*sum(MY^2) + 2*sum(yw^2) + 3*sw^2
        float sumMw2 = fin[0] * fin[0] + fin[3] * fin[3] + fin[5] * fin[5]
                     + 2.f * (fin[1] * fin[1] + fin[2] * fin[2] + fin[4] * fin[4]);
        float summw2 = fin[6] * fin[6] + fin[7] * fin[7] + fin[8] * fin[8];
        float sumyw2 = fin[9] * fin[9] + fin[10] * fin[10] + fin[11] * fin[11];
        float sumMY2 = 0.f;
#pragma unroll
        for (int k = 12; k < 21; k++) sumMY2 += fin[k] * fin[k];
        float sw = fin[21];
        float sc2 = 3.f * sumMw2 + 6.f * summw2 + 2.f * sumMY2 + 2.f * sumyw2 + 3.f * sw * sw;
        float sc = sqrtf(sc2);
        s_scale = sc;
        s_inv_scale = 1.f / sc;
    }
    __syncthreads();

    // Assemble + write Qn: 169 entries, 128 threads -> up to 2 entries each
    float* Qn      = out;                           // [B][13][13]
    float* scales  = out + (size_t)BB * 169;        // [B]
    float* offsets = out + (size_t)BB * 169 + BB;   // [B]

    const float inv_sc = s_inv_scale;
    for (int e = tid; e < 169; e += NTH) {
        int r = e / 13;
        int c = e % 13;
        float v = 0.f;
        if (r >= 1 && r <= 9) {
            int a = r - 1;
            int i = a / 3, k = a % 3;
            if (c >= 1 && c <= 9) {
                int bq = c - 1;
                int j = bq / 3, l = bq % 3;
                if (k == l) v = fin[sym_idx(i, j)];       // Qcc
            } else if (c >= 10) {
                int l = c - 10;
                if (k == l) v = -fin[6 + i];              // Qct
            } else { // c == 0
                v = -fin[12 + i * 3 + k];                 // Qch
            }
        } else if (r >= 10) {
            int i_t = r - 10;
            if (c >= 1 && c <= 9) {
                int a = c - 1;
                int i = a / 3, k = a % 3;
                if (k == i_t) v = -fin[6 + i];            // Qct^T
            } else if (c >= 10) {
                if (r == c) v = fin[21];                  // Qtt
            } else { // c == 0
                v = fin[9 + i_t];                         // yw
            }
        } else { // r == 0
            if (c >= 1 && c <= 9) {
                int a = c - 1;
                v = -fin[12 + a];                         // Qch row
            } else if (c >= 10) {
                v = fin[9 + (c - 10)];                    // yw row
            }
        }
        Qn[(size_t)b * 169 + e] = v * inv_sc;
    }
    if (tid == 0) {
        scales[b]  = s_scale;
        offsets[b] = fin[22];
    }
}

extern "C" void kernel_launch(void* const* d_in, const int* in_sizes, int n_in,
                              void* d_out, int out_size) {
    const float* src = (const float*)d_in[0];
    const float* trg = (const float*)d_in[1];
    const float* wts = (const float*)d_in[2];
    float* out = (float*)d_out;
    locblock_kernel<<<BB, NTH>>>(src, trg, wts, out);
}